// round 2
// baseline (speedup 1.0000x reference)
#include <cuda_runtime.h>

#define TPB 128   // threads per block; each thread handles 2 batch rows

typedef unsigned long long f2;   // packed (lane0, lane1) f32x2

__device__ __forceinline__ f2 f2pack(float a, float b) {
    f2 r; asm("mov.b64 %0,{%1,%2};" : "=l"(r) : "f"(a), "f"(b)); return r;
}
__device__ __forceinline__ void f2unpack(f2 v, float& a, float& b) {
    asm("mov.b64 {%0,%1},%2;" : "=f"(a), "=f"(b) : "l"(v));
}
__device__ __forceinline__ f2 f2mul(f2 a, f2 b) {
    f2 r; asm("mul.rn.f32x2 %0,%1,%2;" : "=l"(r) : "l"(a), "l"(b)); return r;
}
__device__ __forceinline__ f2 f2add(f2 a, f2 b) {
    f2 r; asm("add.rn.f32x2 %0,%1,%2;" : "=l"(r) : "l"(a), "l"(b)); return r;
}
__device__ __forceinline__ f2 f2fma(f2 a, f2 b, f2 c) {
    f2 r; asm("fma.rn.f32x2 %0,%1,%2,%3;" : "=l"(r) : "l"(a), "l"(b), "l"(c)); return r;
}
__device__ __forceinline__ f2 f2neg(f2 a) {
    f2 r; asm("xor.b64 %0,%1,%2;" : "=l"(r) : "l"(a), "l"(0x8000000080000000ULL)); return r;
}
__device__ __forceinline__ float fsqrt_ap(float x) {
    float r; asm("sqrt.approx.f32 %0,%1;" : "=f"(r) : "f"(x)); return r;
}

struct C2 { f2 r, i; };
struct MC { f2 ar, ai, nai, cr, ci, nci, ct, st, nst; };

// rotation coefficients for one mode, both lanes (data-dependent)
__device__ __forceinline__ MC mkmc(float tha, float thb, float pha, float phb) {
    float sta, cta, stb, ctb, spa, cpa, spb, cpb;
    __sincosf(tha, &sta, &cta); __sincosf(thb, &stb, &ctb);
    __sincosf(pha, &spa, &cpa); __sincosf(phb, &spb, &cpb);
    MC m;
    m.ct = f2pack(cta, ctb); m.st = f2pack(sta, stb);
    f2 cp = f2pack(cpa, cpb), sp = f2pack(spa, spb);
    m.ar = f2mul(cp, m.ct); m.ai = f2mul(sp, m.ct);
    m.cr = f2mul(cp, m.st); m.ci = f2mul(sp, m.st);
    m.nai = f2neg(m.ai); m.nci = f2neg(m.ci); m.nst = f2neg(m.st);
    return m;
}

// precomputed uniform data: [0..4] = u0,u1,u2,v3,v4 (broadcast); then 4 MCs (9 each)
__device__ unsigned long long g_pre[5 + 4 * 9];

__device__ __forceinline__ MC ldmc(int off) {
    const unsigned long long* p = g_pre + off;
    MC m;
    m.ar  = __ldg(p + 0); m.ai  = __ldg(p + 1); m.nai = __ldg(p + 2);
    m.cr  = __ldg(p + 3); m.ci  = __ldg(p + 4); m.nci = __ldg(p + 5);
    m.ct  = __ldg(p + 6); m.st  = __ldg(p + 7); m.nst = __ldg(p + 8);
    return m;
}

// full complex-complex Givens rotation on packed state
__device__ __forceinline__ void rot_cc(C2& pi, C2& pj, const MC& m) {
    f2 nir = f2fma(m.ar, pi.r, f2fma(m.nai, pi.i, f2mul(m.nst, pj.r)));
    f2 nii = f2fma(m.ar, pi.i, f2fma(m.ai,  pi.r, f2mul(m.nst, pj.i)));
    f2 njr = f2fma(m.cr, pi.r, f2fma(m.nci, pi.i, f2mul(m.ct,  pj.r)));
    f2 nji = f2fma(m.cr, pi.i, f2fma(m.ci,  pi.r, f2mul(m.ct,  pj.i)));
    pi.r = nir; pi.i = nii; pj.r = njr; pj.i = nji;
}
// pi complex, pj == 0  -> both complex
__device__ __forceinline__ void rot_c0(C2& pi, C2& pj, const MC& m) {
    f2 nir = f2fma(m.ar, pi.r, f2mul(m.nai, pi.i));
    f2 nii = f2fma(m.ar, pi.i, f2mul(m.ai,  pi.r));
    pj.r   = f2fma(m.cr, pi.r, f2mul(m.nci, pi.i));
    pj.i   = f2fma(m.cr, pi.i, f2mul(m.ci,  pi.r));
    pi.r = nir; pi.i = nii;
}
// pi real w, pj complex -> both complex
__device__ __forceinline__ void rot_rc(f2 w, C2& pi, C2& pj, const MC& m) {
    pi.r = f2fma(m.ar, w, f2mul(m.nst, pj.r));
    pi.i = f2fma(m.ai, w, f2mul(m.nst, pj.i));
    f2 njr = f2fma(m.cr, w, f2mul(m.ct, pj.r));
    f2 nji = f2fma(m.ci, w, f2mul(m.ct, pj.i));
    pj.r = njr; pj.i = nji;
}

// ---------------- precompute kernel (1 warp, uniform work) ----------------
__global__ void pre_kernel(const float* __restrict__ pphi,
                           const float* __restrict__ pth) {
    if (threadIdx.x != 0) return;
    auto dup = [](float x) {
        unsigned u = __float_as_uint(x);
        return ((unsigned long long)u << 32) | (unsigned long long)u;
    };
    float st0 = sinf(pth[0]), ct0 = cosf(pth[0]);
    float st2 = sinf(pth[2]), ct2 = cosf(pth[2]);
    float st3 = sinf(pth[3]), ct3 = cosf(pth[3]);
    // state after uniform modes 0-3 acting on e0/e3 (mode1 hits zero rows)
    g_pre[0] = dup(ct0);
    g_pre[1] = dup(ct2 * st0);
    g_pre[2] = dup(st2 * st0);
    g_pre[3] = dup(ct3);
    g_pre[4] = dup(st3);
    const int offs[4] = {5, 14, 23, 32};
    const float ths[4] = {pth[4], pth[5], pth[6], pth[7]};
    for (int q = 0; q < 4; q++) {
        float ct = cosf(ths[q]), st = sinf(ths[q]);
        float cp = cosf(pphi[q]), sp = sinf(pphi[q]);
        float ar = cp * ct, ai = sp * ct, cr = cp * st, ci = sp * st;
        unsigned long long* o = g_pre + offs[q];
        o[0] = dup(ar); o[1] = dup(ai); o[2] = dup(-ai);
        o[3] = dup(cr); o[4] = dup(ci); o[5] = dup(-ci);
        o[6] = dup(ct); o[7] = dup(st); o[8] = dup(-st);
    }
}

// ---------------- main kernel ----------------
__global__ __launch_bounds__(TPB)
void bqnn_main(const float* __restrict__ x,
               const float* __restrict__ ink,
               const float* __restrict__ inb,
               float* __restrict__ out,
               int batch) {
    __shared__ float sout[TPB * 30];
    const int t = threadIdx.x;
    const int base = blockIdx.x * (TPB * 2);
    const int r0 = base + 2 * t;

    // ---- load 2 rows of x (24 contiguous floats) + k/b, compute xs ----
    float xa[12], xb[12];
    {
        float4 kv[3], bv[3], xv[6];
        kv[0] = __ldg((const float4*)(ink + 0));
        kv[1] = __ldg((const float4*)(ink + 4));
        kv[2] = __ldg((const float4*)(ink + 8));
        bv[0] = __ldg((const float4*)(inb + 0));
        bv[1] = __ldg((const float4*)(inb + 4));
        bv[2] = __ldg((const float4*)(inb + 8));
        if (r0 + 2 <= batch) {
            const float4* xp = (const float4*)(x + (size_t)r0 * 12);
#pragma unroll
            for (int i = 0; i < 6; i++) xv[i] = xp[i];
        } else {
#pragma unroll
            for (int i = 0; i < 6; i++) xv[i] = make_float4(0.f, 0.f, 0.f, 0.f);
            if (r0 < batch) {
                const float4* xp = (const float4*)(x + (size_t)r0 * 12);
                xv[0] = xp[0]; xv[1] = xp[1]; xv[2] = xp[2];
            }
        }
        const float* kk = (const float*)kv;
        const float* bb = (const float*)bv;
        const float* xf = (const float*)xv;
#pragma unroll
        for (int i = 0; i < 12; i++) {
            xa[i] = fmaf(xf[i],      kk[i], bb[i]);
            xb[i] = fmaf(xf[i + 12], kk[i], bb[i]);
        }
    }

    // ---- precomputed post-mode-3 state (uniform, broadcast packs) ----
    f2 U0 = __ldg(g_pre + 0), U1 = __ldg(g_pre + 1), U2 = __ldg(g_pre + 2);
    f2 V3 = __ldg(g_pre + 3), V4 = __ldg(g_pre + 4);

    C2 A0, A1, A2, A3, A4, A5;     // column 0
    C2 B1, B2, B3, B4, B5;         // column 3 (B0 stays real)
    f2 B0r, B1r, B2r, B3r;

    // mode4 [0,1] (data): c0 rows (u0,u1) real-real -> complex; c3 untouched
    {
        MC m = mkmc(xa[3], xb[3], xa[0], xb[0]);
        A0.r = f2fma(m.ar, U0, f2mul(m.nst, U1)); A0.i = f2mul(m.ai, U0);
        A1.r = f2fma(m.cr, U0, f2mul(m.ct,  U1)); A1.i = f2mul(m.ci, U0);
    }
    // mode5 [2,3] (data): c0 (u2, 0); c3 (0, v3)
    {
        MC m = mkmc(xa[4], xb[4], xa[1], xb[1]);
        A2.r = f2mul(m.ar, U2); A2.i = f2mul(m.ai, U2);
        A3.r = f2mul(m.cr, U2); A3.i = f2mul(m.ci, U2);
        B2r = f2mul(m.nst, V3); B3r = f2mul(m.ct, V3);
    }
    // mode6 [4,5] (data): c0 rows zero; c3 (v4, 0)
    {
        MC m = mkmc(xa[5], xb[5], xa[2], xb[2]);
        B4.r = f2mul(m.ar, V4); B4.i = f2mul(m.ai, V4);
        B5.r = f2mul(m.cr, V4); B5.i = f2mul(m.ci, V4);
    }
    // mode7 [1,2] (uniform): c0 full; c3 (0, B2r real) -> stays real
    {
        MC u = ldmc(5);
        rot_cc(A1, A2, u);
        B1r = f2mul(u.nst, B2r);
        B2r = f2mul(u.ct,  B2r);
    }
    // mode8 [3,4] (uniform): c0 (A3 complex, 0); c3 (B3r real, B4 complex)
    {
        MC u = ldmc(14);
        rot_c0(A3, A4, u);
        rot_rc(B3r, B3, B4, u);
    }
    // mode9 [0,1] (data): c0 full; c3 (0, B1r real) -> stays real
    {
        MC m = mkmc(xa[9], xb[9], xa[6], xb[6]);
        rot_cc(A0, A1, m);
        B0r = f2mul(m.nst, B1r);
        B1r = f2mul(m.ct,  B1r);
    }
    // mode10 [2,3] (data): c0 full; c3 (B2r real, B3 complex)
    {
        MC m = mkmc(xa[10], xb[10], xa[7], xb[7]);
        rot_cc(A2, A3, m);
        rot_rc(B2r, B2, B3, m);
    }
    // mode11 [4,5] (data): c0 (A4 complex, 0); c3 full
    {
        MC m = mkmc(xa[11], xb[11], xa[8], xb[8]);
        rot_c0(A4, A5, m);
        rot_cc(B4, B5, m);
    }
    // mode12 [1,2] (uniform): c0 full; c3 (B1r real, B2 complex)
    {
        MC u = ldmc(23);
        rot_cc(A1, A2, u);
        rot_rc(B1r, B1, B2, u);
    }
    // mode13 [3,4] (uniform): c0 full; c3 full
    {
        MC u = ldmc(32);
        rot_cc(A3, A4, u);
        rot_cc(B3, B4, u);
    }

    // ---- 15 pair amplitudes (packed) ----
    f2 ZERO = f2pack(0.f, 0.f);
    f2 a_r[6] = {A0.r, A1.r, A2.r, A3.r, A4.r, A5.r};
    f2 a_i[6] = {A0.i, A1.i, A2.i, A3.i, A4.i, A5.i};
    f2 b_r[6] = {B0r,  B1.r, B2.r, B3.r, B4.r, B5.r};
    f2 b_i[6] = {ZERO, B1.i, B2.i, B3.i, B4.i, B5.i};
    f2 na_i[6], nb_i[6];
#pragma unroll
    for (int k = 0; k < 6; k++) { na_i[k] = f2neg(a_i[k]); nb_i[k] = f2neg(b_i[k]); }

    const int PA[15] = {0, 0, 0, 0, 0, 1, 1, 1, 1, 2, 2, 2, 3, 3, 4};
    const int PB[15] = {1, 2, 3, 4, 5, 2, 3, 4, 5, 3, 4, 5, 4, 5, 5};
    f2 mag[15];
    f2 sum = ZERO;
#pragma unroll
    for (int p = 0; p < 15; p++) {
        const int i = PA[p], j = PB[p];
        // re = ar_i*br_j - ai_i*bi_j + ar_j*br_i - ai_j*bi_i
        f2 re = f2fma(a_r[i], b_r[j],
                 f2fma(na_i[i], b_i[j],
                  f2fma(a_r[j], b_r[i], f2mul(nb_i[i], a_i[j]))));
        // im = ar_i*bi_j + ai_i*br_j + ar_j*bi_i + ai_j*br_i
        f2 im = f2fma(a_r[i], b_i[j],
                 f2fma(a_i[i], b_r[j],
                  f2fma(a_r[j], b_i[i], f2mul(a_i[j], b_r[i]))));
        mag[p] = f2fma(re, re, f2mul(im, im));
        sum = f2add(sum, mag[p]);
    }

    float sa, sb;
    f2unpack(sum, sa, sb);
    float rna = __fdividef(1.0f, fmaxf(fsqrt_ap(sa), 1e-12f));
    float rnb = __fdividef(1.0f, fmaxf(fsqrt_ap(sb), 1e-12f));

#pragma unroll
    for (int p = 0; p < 15; p++) {
        float ma, mb;
        f2unpack(mag[p], ma, mb);
        sout[30 * t + p]      = fsqrt_ap(ma) * rna;
        sout[30 * t + 15 + p] = fsqrt_ap(mb) * rnb;
    }

    __syncthreads();

    // ---- coalesced copy-out ----
    int rows = batch - base;
    if (rows > TPB * 2) rows = TPB * 2;
    float* gout = out + (size_t)base * 15;
    if (rows == TPB * 2) {
        const float4* s4 = (const float4*)sout;
        float4* g4 = (float4*)gout;
#pragma unroll
        for (int q = 0; q < 8; q++) {
            int idx = t + q * TPB;
            if (idx < (TPB * 30) / 4) g4[idx] = s4[idx];
        }
    } else if (rows > 0) {
        for (int idx = t; idx < rows * 15; idx += TPB) gout[idx] = sout[idx];
    }
}

extern "C" void kernel_launch(void* const* d_in, const int* in_sizes, int n_in,
                              void* d_out, int out_size) {
    const float* x    = (const float*)d_in[0];
    const float* pphi = (const float*)d_in[1];
    const float* pth  = (const float*)d_in[2];
    const float* ink  = (const float*)d_in[3];
    const float* inb  = (const float*)d_in[4];
    float* out = (float*)d_out;

    int batch = in_sizes[0] / 12;
    int grid  = (batch + TPB * 2 - 1) / (TPB * 2);
    pre_kernel<<<1, 32>>>(pphi, pth);
    bqnn_main<<<grid, TPB>>>(x, ink, inb, out, batch);
}

// round 3
// speedup vs baseline: 1.1572x; 1.1572x over previous
#include <cuda_runtime.h>

#define TPB 128   // threads per block; each thread handles 2 batch rows

typedef unsigned long long f2;   // packed (lane0, lane1) f32x2

__device__ __forceinline__ f2 f2pack(float a, float b) {
    f2 r; asm("mov.b64 %0,{%1,%2};" : "=l"(r) : "f"(a), "f"(b)); return r;
}
__device__ __forceinline__ f2 f2dup(float a) { return f2pack(a, a); }
__device__ __forceinline__ void f2unpack(f2 v, float& a, float& b) {
    asm("mov.b64 {%0,%1},%2;" : "=f"(a), "=f"(b) : "l"(v));
}
__device__ __forceinline__ f2 f2mul(f2 a, f2 b) {
    f2 r; asm("mul.rn.f32x2 %0,%1,%2;" : "=l"(r) : "l"(a), "l"(b)); return r;
}
__device__ __forceinline__ f2 f2add(f2 a, f2 b) {
    f2 r; asm("add.rn.f32x2 %0,%1,%2;" : "=l"(r) : "l"(a), "l"(b)); return r;
}
__device__ __forceinline__ f2 f2fma(f2 a, f2 b, f2 c) {
    f2 r; asm("fma.rn.f32x2 %0,%1,%2,%3;" : "=l"(r) : "l"(a), "l"(b), "l"(c)); return r;
}
__device__ __forceinline__ f2 f2neg(f2 a) {
    f2 r; asm("xor.b64 %0,%1,%2;" : "=l"(r) : "l"(a), "l"(0x8000000080000000ULL)); return r;
}
__device__ __forceinline__ float fsqrt_ap(float x) {
    float r; asm("sqrt.approx.f32 %0,%1;" : "=f"(r) : "f"(x)); return r;
}
__device__ __forceinline__ float frsqrt_ap(float x) {
    float r; asm("rsqrt.approx.f32 %0,%1;" : "=f"(r) : "f"(x)); return r;
}

struct C2 { f2 r, i; };
struct MC { f2 ar, ai, nai, cr, ci, nci, ct, st, nst; };

// data-dependent mode: two lanes, independent angles
__device__ __forceinline__ MC mkmc(float tha, float thb, float pha, float phb) {
    float sta, cta, stb, ctb, spa, cpa, spb, cpb;
    __sincosf(tha, &sta, &cta); __sincosf(thb, &stb, &ctb);
    __sincosf(pha, &spa, &cpa); __sincosf(phb, &spb, &cpb);
    MC m;
    m.ct = f2pack(cta, ctb); m.st = f2pack(sta, stb);
    f2 cp = f2pack(cpa, cpb), sp = f2pack(spa, spb);
    m.ar = f2mul(cp, m.ct); m.ai = f2mul(sp, m.ct);
    m.cr = f2mul(cp, m.st); m.ci = f2mul(sp, m.st);
    m.nai = f2neg(m.ai); m.nci = f2neg(m.ci); m.nst = f2neg(m.st);
    return m;
}

// uniform mode: same angle in both lanes (scalar math, then dup)
__device__ __forceinline__ MC mkmc_u(float th, float ph) {
    float st, ct, sp, cp;
    __sincosf(th, &st, &ct); __sincosf(ph, &sp, &cp);
    MC m;
    m.ct = f2dup(ct);        m.st = f2dup(st);        m.nst = f2dup(-st);
    m.ar = f2dup(cp * ct);   m.ai = f2dup(sp * ct);   m.nai = f2dup(-sp * ct);
    m.cr = f2dup(cp * st);   m.ci = f2dup(sp * st);   m.nci = f2dup(-sp * st);
    return m;
}

// full complex-complex Givens rotation on packed state
__device__ __forceinline__ void rot_cc(C2& pi, C2& pj, const MC& m) {
    f2 nir = f2fma(m.ar, pi.r, f2fma(m.nai, pi.i, f2mul(m.nst, pj.r)));
    f2 nii = f2fma(m.ar, pi.i, f2fma(m.ai,  pi.r, f2mul(m.nst, pj.i)));
    f2 njr = f2fma(m.cr, pi.r, f2fma(m.nci, pi.i, f2mul(m.ct,  pj.r)));
    f2 nji = f2fma(m.cr, pi.i, f2fma(m.ci,  pi.r, f2mul(m.ct,  pj.i)));
    pi.r = nir; pi.i = nii; pj.r = njr; pj.i = nji;
}
// pi complex, pj == 0 -> both complex
__device__ __forceinline__ void rot_c0(C2& pi, C2& pj, const MC& m) {
    f2 nir = f2fma(m.ar, pi.r, f2mul(m.nai, pi.i));
    f2 nii = f2fma(m.ar, pi.i, f2mul(m.ai,  pi.r));
    pj.r   = f2fma(m.cr, pi.r, f2mul(m.nci, pi.i));
    pj.i   = f2fma(m.cr, pi.i, f2mul(m.ci,  pi.r));
    pi.r = nir; pi.i = nii;
}
// pi real w, pj complex -> both complex
__device__ __forceinline__ void rot_rc(f2 w, C2& pi, C2& pj, const MC& m) {
    pi.r = f2fma(m.ar, w, f2mul(m.nst, pj.r));
    pi.i = f2fma(m.ai, w, f2mul(m.nst, pj.i));
    f2 njr = f2fma(m.cr, w, f2mul(m.ct, pj.r));
    f2 nji = f2fma(m.ci, w, f2mul(m.ct, pj.i));
    pj.r = njr; pj.i = nji;
}

__global__ __launch_bounds__(TPB, 8)
void bqnn_main(const float* __restrict__ x,
               const float* __restrict__ pphi,
               const float* __restrict__ pth,
               const float* __restrict__ ink,
               const float* __restrict__ inb,
               float* __restrict__ out,
               int batch) {
    __shared__ float sout[TPB * 30];      // unnormalized |amp|
    __shared__ float srn[TPB * 2];        // per-row 1/norm
    const int t = threadIdx.x;
    const int base = blockIdx.x * (TPB * 2);
    const int r0 = base + 2 * t;

    // ---- load 2 rows of x (24 contiguous floats) + k/b, compute xs ----
    float xa[12], xb[12];
    {
        float4 kv[3], bv[3], xv[6];
        kv[0] = __ldg((const float4*)(ink + 0));
        kv[1] = __ldg((const float4*)(ink + 4));
        kv[2] = __ldg((const float4*)(ink + 8));
        bv[0] = __ldg((const float4*)(inb + 0));
        bv[1] = __ldg((const float4*)(inb + 4));
        bv[2] = __ldg((const float4*)(inb + 8));
        if (r0 + 2 <= batch) {
            const float4* xp = (const float4*)(x + (size_t)r0 * 12);
#pragma unroll
            for (int i = 0; i < 6; i++) xv[i] = xp[i];
        } else {
#pragma unroll
            for (int i = 0; i < 6; i++) xv[i] = make_float4(0.f, 0.f, 0.f, 0.f);
            if (r0 < batch) {
                const float4* xp = (const float4*)(x + (size_t)r0 * 12);
                xv[0] = xp[0]; xv[1] = xp[1]; xv[2] = xp[2];
            }
        }
        const float* kk = (const float*)kv;
        const float* bb = (const float*)bv;
        const float* xf = (const float*)xv;
#pragma unroll
        for (int i = 0; i < 12; i++) {
            xa[i] = fmaf(xf[i],      kk[i], bb[i]);
            xb[i] = fmaf(xf[i + 12], kk[i], bb[i]);
        }
    }

    // ---- uniform prelude (modes 0-3 acting on e0/e3) computed per thread ----
    float th0 = __ldg(pth + 0), th2 = __ldg(pth + 2), th3 = __ldg(pth + 3);
    float st0, ct0, st2, ct2, st3, ct3;
    __sincosf(th0, &st0, &ct0);
    __sincosf(th2, &st2, &ct2);
    __sincosf(th3, &st3, &ct3);
    f2 U0 = f2dup(ct0);
    f2 U1 = f2dup(ct2 * st0);
    f2 U2 = f2dup(st2 * st0);
    f2 V3 = f2dup(ct3);
    f2 V4 = f2dup(st3);

    C2 A0, A1, A2, A3, A4, A5;     // column 0
    C2 B1, B2, B3, B4, B5;         // column 3 (B0 stays real)
    f2 B0r, B1r, B2r, B3r;

    // mode4 [0,1] (data): c0 rows (u0,u1) real-real -> complex
    {
        MC m = mkmc(xa[3], xb[3], xa[0], xb[0]);
        A0.r = f2fma(m.ar, U0, f2mul(m.nst, U1)); A0.i = f2mul(m.ai, U0);
        A1.r = f2fma(m.cr, U0, f2mul(m.ct,  U1)); A1.i = f2mul(m.ci, U0);
    }
    // mode5 [2,3] (data): c0 (u2, 0); c3 (0, v3)
    {
        MC m = mkmc(xa[4], xb[4], xa[1], xb[1]);
        A2.r = f2mul(m.ar, U2); A2.i = f2mul(m.ai, U2);
        A3.r = f2mul(m.cr, U2); A3.i = f2mul(m.ci, U2);
        B2r = f2mul(m.nst, V3); B3r = f2mul(m.ct, V3);
    }
    // mode6 [4,5] (data): c0 rows zero; c3 (v4, 0)
    {
        MC m = mkmc(xa[5], xb[5], xa[2], xb[2]);
        B4.r = f2mul(m.ar, V4); B4.i = f2mul(m.ai, V4);
        B5.r = f2mul(m.cr, V4); B5.i = f2mul(m.ci, V4);
    }
    // mode7 [1,2] (uniform): c0 full; c3 (0, B2r real) -> stays real
    {
        MC u = mkmc_u(__ldg(pth + 4), __ldg(pphi + 0));
        rot_cc(A1, A2, u);
        B1r = f2mul(u.nst, B2r);
        B2r = f2mul(u.ct,  B2r);
    }
    // mode8 [3,4] (uniform): c0 (A3 complex, 0); c3 (B3r real, B4 complex)
    {
        MC u = mkmc_u(__ldg(pth + 5), __ldg(pphi + 1));
        rot_c0(A3, A4, u);
        rot_rc(B3r, B3, B4, u);
    }
    // mode9 [0,1] (data): c0 full; c3 (0, B1r real) -> stays real
    {
        MC m = mkmc(xa[9], xb[9], xa[6], xb[6]);
        rot_cc(A0, A1, m);
        B0r = f2mul(m.nst, B1r);
        B1r = f2mul(m.ct,  B1r);
    }
    // mode10 [2,3] (data): c0 full; c3 (B2r real, B3 complex)
    {
        MC m = mkmc(xa[10], xb[10], xa[7], xb[7]);
        rot_cc(A2, A3, m);
        rot_rc(B2r, B2, B3, m);
    }
    // mode11 [4,5] (data): c0 (A4 complex, 0); c3 full
    {
        MC m = mkmc(xa[11], xb[11], xa[8], xb[8]);
        rot_c0(A4, A5, m);
        rot_cc(B4, B5, m);
    }
    // mode12 [1,2] (uniform): c0 full; c3 (B1r real, B2 complex)
    {
        MC u = mkmc_u(__ldg(pth + 6), __ldg(pphi + 2));
        rot_cc(A1, A2, u);
        rot_rc(B1r, B1, B2, u);
    }
    // mode13 [3,4] (uniform): c0 full; c3 full
    {
        MC u = mkmc_u(__ldg(pth + 7), __ldg(pphi + 3));
        rot_cc(A3, A4, u);
        rot_cc(B3, B4, u);
    }

    // ---- 15 pair amplitudes (packed); store unnormalized |amp| to smem ----
    f2 ZERO = f2dup(0.f);
    f2 a_r[6] = {A0.r, A1.r, A2.r, A3.r, A4.r, A5.r};
    f2 a_i[6] = {A0.i, A1.i, A2.i, A3.i, A4.i, A5.i};
    f2 b_r[6] = {B0r,  B1.r, B2.r, B3.r, B4.r, B5.r};
    f2 b_i[6] = {ZERO, B1.i, B2.i, B3.i, B4.i, B5.i};
    f2 na_i[6];
#pragma unroll
    for (int k = 0; k < 6; k++) na_i[k] = f2neg(a_i[k]);

    const int PA[15] = {0, 0, 0, 0, 0, 1, 1, 1, 1, 2, 2, 2, 3, 3, 4};
    const int PB[15] = {1, 2, 3, 4, 5, 2, 3, 4, 5, 3, 4, 5, 4, 5, 5};
    f2 sum = ZERO;
#pragma unroll
    for (int p = 0; p < 15; p++) {
        const int i = PA[p], j = PB[p];
        // re = ar_i*br_j - ai_i*bi_j + ar_j*br_i - ai_j*bi_i
        f2 re = f2fma(a_r[i], b_r[j],
                 f2fma(na_i[i], b_i[j],
                  f2fma(a_r[j], b_r[i], f2mul(na_i[j], b_i[i]))));
        // im = ar_i*bi_j + ai_i*br_j + ar_j*bi_i + ai_j*br_i
        f2 im = f2fma(a_r[i], b_i[j],
                 f2fma(a_i[i], b_r[j],
                  f2fma(a_r[j], b_i[i], f2mul(a_i[j], b_r[i]))));
        f2 mag = f2fma(re, re, f2mul(im, im));
        sum = f2add(sum, mag);
        float ma, mb;
        f2unpack(mag, ma, mb);
        sout[30 * t + p]      = fsqrt_ap(ma);
        sout[30 * t + 15 + p] = fsqrt_ap(mb);
    }

    {
        float sa, sb;
        f2unpack(sum, sa, sb);
        srn[2 * t]     = frsqrt_ap(fmaxf(sa, 1e-24f));
        srn[2 * t + 1] = frsqrt_ap(fmaxf(sb, 1e-24f));
    }

    __syncthreads();

    // ---- coalesced, normalized copy-out ----
    int rows = batch - base;
    if (rows > TPB * 2) rows = TPB * 2;
    float* gout = out + (size_t)base * 15;
    if (rows == TPB * 2) {
        const float4* s4 = (const float4*)sout;
        float4* g4 = (float4*)gout;
#pragma unroll
        for (int q = 0; q < 8; q++) {
            int idx = t + q * TPB;
            if (idx < (TPB * 30) / 4) {
                float4 v = s4[idx];
                int e = idx * 4;
                v.x *= srn[(e + 0) / 15];
                v.y *= srn[(e + 1) / 15];
                v.z *= srn[(e + 2) / 15];
                v.w *= srn[(e + 3) / 15];
                g4[idx] = v;
            }
        }
    } else if (rows > 0) {
        for (int idx = t; idx < rows * 15; idx += TPB)
            gout[idx] = sout[idx] * srn[idx / 15];
    }
}

extern "C" void kernel_launch(void* const* d_in, const int* in_sizes, int n_in,
                              void* d_out, int out_size) {
    const float* x    = (const float*)d_in[0];
    const float* pphi = (const float*)d_in[1];
    const float* pth  = (const float*)d_in[2];
    const float* ink  = (const float*)d_in[3];
    const float* inb  = (const float*)d_in[4];
    float* out = (float*)d_out;

    int batch = in_sizes[0] / 12;
    int grid  = (batch + TPB * 2 - 1) / (TPB * 2);
    bqnn_main<<<grid, TPB>>>(x, pphi, pth, ink, inb, out, batch);
}

// round 4
// speedup vs baseline: 1.4060x; 1.2149x over previous
#include <cuda_runtime.h>

#define TPB 128   // threads per block; each thread handles 2 batch rows

typedef unsigned long long f2;   // packed (lane0, lane1) f32x2

__device__ __forceinline__ f2 f2pack(float a, float b) {
    f2 r; asm("mov.b64 %0,{%1,%2};" : "=l"(r) : "f"(a), "f"(b)); return r;
}
__device__ __forceinline__ f2 f2dup(float a) { return f2pack(a, a); }
__device__ __forceinline__ void f2unpack(f2 v, float& a, float& b) {
    asm("mov.b64 {%0,%1},%2;" : "=f"(a), "=f"(b) : "l"(v));
}
__device__ __forceinline__ f2 f2mul(f2 a, f2 b) {
    f2 r; asm("mul.rn.f32x2 %0,%1,%2;" : "=l"(r) : "l"(a), "l"(b)); return r;
}
__device__ __forceinline__ f2 f2add(f2 a, f2 b) {
    f2 r; asm("add.rn.f32x2 %0,%1,%2;" : "=l"(r) : "l"(a), "l"(b)); return r;
}
__device__ __forceinline__ f2 f2fma(f2 a, f2 b, f2 c) {
    f2 r; asm("fma.rn.f32x2 %0,%1,%2,%3;" : "=l"(r) : "l"(a), "l"(b), "l"(c)); return r;
}
__device__ __forceinline__ f2 f2neg(f2 a) {
    f2 r; asm("xor.b64 %0,%1,%2;" : "=l"(r) : "l"(a), "l"(0x8000000080000000ULL)); return r;
}
__device__ __forceinline__ float fsqrt_ap(float x) {
    float r; asm("sqrt.approx.f32 %0,%1;" : "=f"(r) : "f"(x)); return r;
}
__device__ __forceinline__ float frsqrt_ap(float x) {
    float r; asm("rsqrt.approx.f32 %0,%1;" : "=f"(r) : "f"(x)); return r;
}

struct C2 { f2 r, i; };
struct MC { f2 ar, ai, nai, cr, ci, nci, ct, st, nst; };

// data-dependent mode: two lanes, independent angles
__device__ __forceinline__ MC mkmc(float tha, float thb, float pha, float phb) {
    float sta, cta, stb, ctb, spa, cpa, spb, cpb;
    __sincosf(tha, &sta, &cta); __sincosf(thb, &stb, &ctb);
    __sincosf(pha, &spa, &cpa); __sincosf(phb, &spb, &cpb);
    MC m;
    m.ct = f2pack(cta, ctb); m.st = f2pack(sta, stb);
    f2 cp = f2pack(cpa, cpb), sp = f2pack(spa, spb);
    m.ar = f2mul(cp, m.ct); m.ai = f2mul(sp, m.ct);
    m.cr = f2mul(cp, m.st); m.ci = f2mul(sp, m.st);
    m.nai = f2neg(m.ai); m.nci = f2neg(m.ci); m.nst = f2neg(m.st);
    return m;
}

// full complex-complex Givens rotation on packed state
__device__ __forceinline__ void rot_cc(C2& pi, C2& pj, const MC& m) {
    f2 nir = f2fma(m.ar, pi.r, f2fma(m.nai, pi.i, f2mul(m.nst, pj.r)));
    f2 nii = f2fma(m.ar, pi.i, f2fma(m.ai,  pi.r, f2mul(m.nst, pj.i)));
    f2 njr = f2fma(m.cr, pi.r, f2fma(m.nci, pi.i, f2mul(m.ct,  pj.r)));
    f2 nji = f2fma(m.cr, pi.i, f2fma(m.ci,  pi.r, f2mul(m.ct,  pj.i)));
    pi.r = nir; pi.i = nii; pj.r = njr; pj.i = nji;
}
// pi complex, pj == 0 -> both complex
__device__ __forceinline__ void rot_c0(C2& pi, C2& pj, const MC& m) {
    f2 nir = f2fma(m.ar, pi.r, f2mul(m.nai, pi.i));
    f2 nii = f2fma(m.ar, pi.i, f2mul(m.ai,  pi.r));
    pj.r   = f2fma(m.cr, pi.r, f2mul(m.nci, pi.i));
    pj.i   = f2fma(m.cr, pi.i, f2mul(m.ci,  pi.r));
    pi.r = nir; pi.i = nii;
}
// pi real w, pj complex -> both complex
__device__ __forceinline__ void rot_rc(f2 w, C2& pi, C2& pj, const MC& m) {
    pi.r = f2fma(m.ar, w, f2mul(m.nst, pj.r));
    pi.i = f2fma(m.ai, w, f2mul(m.nst, pj.i));
    f2 njr = f2fma(m.cr, w, f2mul(m.ct, pj.r));
    f2 nji = f2fma(m.ci, w, f2mul(m.ct, pj.i));
    pj.r = njr; pj.i = nji;
}

__global__ __launch_bounds__(TPB)
void bqnn_main(const float* __restrict__ x,
               const float* __restrict__ pphi,
               const float* __restrict__ pth,
               const float* __restrict__ ink,
               const float* __restrict__ inb,
               float* __restrict__ out,
               int batch) {
    __shared__ float sout[TPB * 30];
    __shared__ f2 spre[5 + 4 * 9];   // [0..4]=prelude u0,u1,u2,v3,v4; 4 MCs of 9
    const int t = threadIdx.x;
    const int base = blockIdx.x * (TPB * 2);
    const int r0 = base + 2 * t;

    // ---- per-block uniform precompute (threads 0..4) ----
    if (t < 4) {
        float th = __ldg(pth + 4 + t), ph = __ldg(pphi + t);
        float st, ct, sp, cp;
        __sincosf(th, &st, &ct);
        __sincosf(ph, &sp, &cp);
        f2* o = spre + 5 + t * 9;
        o[0] = f2dup(cp * ct); o[1] = f2dup(sp * ct); o[2] = f2dup(-sp * ct);
        o[3] = f2dup(cp * st); o[4] = f2dup(sp * st); o[5] = f2dup(-sp * st);
        o[6] = f2dup(ct);      o[7] = f2dup(st);      o[8] = f2dup(-st);
    } else if (t == 4) {
        float st0, ct0, st2, ct2, st3, ct3;
        __sincosf(__ldg(pth + 0), &st0, &ct0);
        __sincosf(__ldg(pth + 2), &st2, &ct2);
        __sincosf(__ldg(pth + 3), &st3, &ct3);
        spre[0] = f2dup(ct0);
        spre[1] = f2dup(ct2 * st0);
        spre[2] = f2dup(st2 * st0);
        spre[3] = f2dup(ct3);
        spre[4] = f2dup(st3);
    }

    // ---- load 2 rows of x (24 contiguous floats) + k/b, compute xs ----
    float xa[12], xb[12];
    {
        float4 kv[3], bv[3], xv[6];
        kv[0] = __ldg((const float4*)(ink + 0));
        kv[1] = __ldg((const float4*)(ink + 4));
        kv[2] = __ldg((const float4*)(ink + 8));
        bv[0] = __ldg((const float4*)(inb + 0));
        bv[1] = __ldg((const float4*)(inb + 4));
        bv[2] = __ldg((const float4*)(inb + 8));
        if (r0 + 2 <= batch) {
            const float4* xp = (const float4*)(x + (size_t)r0 * 12);
#pragma unroll
            for (int i = 0; i < 6; i++) xv[i] = xp[i];
        } else {
#pragma unroll
            for (int i = 0; i < 6; i++) xv[i] = make_float4(0.f, 0.f, 0.f, 0.f);
            if (r0 < batch) {
                const float4* xp = (const float4*)(x + (size_t)r0 * 12);
                xv[0] = xp[0]; xv[1] = xp[1]; xv[2] = xp[2];
            }
        }
        const float* kk = (const float*)kv;
        const float* bb = (const float*)bv;
        const float* xf = (const float*)xv;
#pragma unroll
        for (int i = 0; i < 12; i++) {
            xa[i] = fmaf(xf[i],      kk[i], bb[i]);
            xb[i] = fmaf(xf[i + 12], kk[i], bb[i]);
        }
    }

    __syncthreads();   // spre ready

    // load MC from shared (broadcast LDS)
    auto ldmc = [&](int off) {
        const f2* p = spre + off;
        MC m;
        m.ar = p[0]; m.ai = p[1]; m.nai = p[2];
        m.cr = p[3]; m.ci = p[4]; m.nci = p[5];
        m.ct = p[6]; m.st = p[7]; m.nst = p[8];
        return m;
    };

    f2 U0 = spre[0], U1 = spre[1], U2 = spre[2];
    f2 V3 = spre[3], V4 = spre[4];

    C2 A0, A1, A2, A3, A4, A5;     // column 0
    C2 B1, B2, B3, B4, B5;         // column 3 (B0 stays real)
    f2 B0r, B1r, B2r, B3r;

    // mode4 [0,1] (data): c0 rows (u0,u1) real-real -> complex
    {
        MC m = mkmc(xa[3], xb[3], xa[0], xb[0]);
        A0.r = f2fma(m.ar, U0, f2mul(m.nst, U1)); A0.i = f2mul(m.ai, U0);
        A1.r = f2fma(m.cr, U0, f2mul(m.ct,  U1)); A1.i = f2mul(m.ci, U0);
    }
    // mode5 [2,3] (data): c0 (u2, 0); c3 (0, v3)
    {
        MC m = mkmc(xa[4], xb[4], xa[1], xb[1]);
        A2.r = f2mul(m.ar, U2); A2.i = f2mul(m.ai, U2);
        A3.r = f2mul(m.cr, U2); A3.i = f2mul(m.ci, U2);
        B2r = f2mul(m.nst, V3); B3r = f2mul(m.ct, V3);
    }
    // mode6 [4,5] (data): c3 (v4, 0)
    {
        MC m = mkmc(xa[5], xb[5], xa[2], xb[2]);
        B4.r = f2mul(m.ar, V4); B4.i = f2mul(m.ai, V4);
        B5.r = f2mul(m.cr, V4); B5.i = f2mul(m.ci, V4);
    }
    // mode7 [1,2] (uniform): c0 full; c3 (0, B2r real) -> stays real
    {
        MC u = ldmc(5);
        rot_cc(A1, A2, u);
        B1r = f2mul(u.nst, B2r);
        B2r = f2mul(u.ct,  B2r);
    }
    // mode8 [3,4] (uniform): c0 (A3 complex, 0); c3 (B3r real, B4 complex)
    {
        MC u = ldmc(14);
        rot_c0(A3, A4, u);
        rot_rc(B3r, B3, B4, u);
    }
    // mode9 [0,1] (data): c0 full; c3 (0, B1r real) -> stays real
    {
        MC m = mkmc(xa[9], xb[9], xa[6], xb[6]);
        rot_cc(A0, A1, m);
        B0r = f2mul(m.nst, B1r);
        B1r = f2mul(m.ct,  B1r);
    }
    // mode10 [2,3] (data): c0 full; c3 (B2r real, B3 complex)
    {
        MC m = mkmc(xa[10], xb[10], xa[7], xb[7]);
        rot_cc(A2, A3, m);
        rot_rc(B2r, B2, B3, m);
    }
    // mode11 [4,5] (data): c0 (A4 complex, 0); c3 full
    {
        MC m = mkmc(xa[11], xb[11], xa[8], xb[8]);
        rot_c0(A4, A5, m);
        rot_cc(B4, B5, m);
    }
    // mode12 [1,2] (uniform): c0 full; c3 (B1r real, B2 complex)
    {
        MC u = ldmc(23);
        rot_cc(A1, A2, u);
        rot_rc(B1r, B1, B2, u);
    }
    // mode13 [3,4] (uniform): c0 full; c3 full
    {
        MC u = ldmc(32);
        rot_cc(A3, A4, u);
        rot_cc(B3, B4, u);
    }

    // ---- 15 pair amplitudes (packed) ----
    f2 ZERO = f2dup(0.f);
    f2 a_r[6] = {A0.r, A1.r, A2.r, A3.r, A4.r, A5.r};
    f2 a_i[6] = {A0.i, A1.i, A2.i, A3.i, A4.i, A5.i};
    f2 b_r[6] = {B0r,  B1.r, B2.r, B3.r, B4.r, B5.r};
    f2 b_i[6] = {ZERO, B1.i, B2.i, B3.i, B4.i, B5.i};
    f2 na_i[6];
#pragma unroll
    for (int k = 0; k < 6; k++) na_i[k] = f2neg(a_i[k]);

    const int PA[15] = {0, 0, 0, 0, 0, 1, 1, 1, 1, 2, 2, 2, 3, 3, 4};
    const int PB[15] = {1, 2, 3, 4, 5, 2, 3, 4, 5, 3, 4, 5, 4, 5, 5};
    f2 mag[15];
    f2 sum = ZERO;
#pragma unroll
    for (int p = 0; p < 15; p++) {
        const int i = PA[p], j = PB[p];
        // re = ar_i*br_j - ai_i*bi_j + ar_j*br_i - ai_j*bi_i
        f2 re = f2fma(a_r[i], b_r[j],
                 f2fma(na_i[i], b_i[j],
                  f2fma(a_r[j], b_r[i], f2mul(na_i[j], b_i[i]))));
        // im = ar_i*bi_j + ai_i*br_j + ar_j*bi_i + ai_j*br_i
        f2 im = f2fma(a_r[i], b_i[j],
                 f2fma(a_i[i], b_r[j],
                  f2fma(a_r[j], b_i[i], f2mul(a_i[j], b_r[i]))));
        mag[p] = f2fma(re, re, f2mul(im, im));
        sum = f2add(sum, mag[p]);
    }

    float sa, sb;
    f2unpack(sum, sa, sb);
    float rna = frsqrt_ap(fmaxf(sa, 1e-24f));
    float rnb = frsqrt_ap(fmaxf(sb, 1e-24f));

#pragma unroll
    for (int p = 0; p < 15; p++) {
        float ma, mb;
        f2unpack(mag[p], ma, mb);
        sout[30 * t + p]      = fsqrt_ap(ma) * rna;
        sout[30 * t + 15 + p] = fsqrt_ap(mb) * rnb;
    }

    __syncthreads();

    // ---- coalesced copy-out ----
    int rows = batch - base;
    if (rows > TPB * 2) rows = TPB * 2;
    float* gout = out + (size_t)base * 15;
    if (rows == TPB * 2) {
        const float4* s4 = (const float4*)sout;
        float4* g4 = (float4*)gout;
#pragma unroll
        for (int q = 0; q < 8; q++) {
            int idx = t + q * TPB;
            if (idx < (TPB * 30) / 4) g4[idx] = s4[idx];
        }
    } else if (rows > 0) {
        for (int idx = t; idx < rows * 15; idx += TPB) gout[idx] = sout[idx];
    }
}

extern "C" void kernel_launch(void* const* d_in, const int* in_sizes, int n_in,
                              void* d_out, int out_size) {
    const float* x    = (const float*)d_in[0];
    const float* pphi = (const float*)d_in[1];
    const float* pth  = (const float*)d_in[2];
    const float* ink  = (const float*)d_in[3];
    const float* inb  = (const float*)d_in[4];
    float* out = (float*)d_out;

    int batch = in_sizes[0] / 12;
    int grid  = (batch + TPB * 2 - 1) / (TPB * 2);
    bqnn_main<<<grid, TPB>>>(x, pphi, pth, ink, inb, out, batch);
}